// round 11
// baseline (speedup 1.0000x reference)
#include <cuda_runtime.h>
#include <cuda_bf16.h>

#define BSZ    640
#define INCH   2048
#define OUTCH  696
#define NS     174
#define CHROWS 320
#define WROWS  704              // OUTCH padded to 64
#define KSPLIT 4
#define KSLICE (INCH / KSPLIT)  // 512

// ---------------- scratch ----------------
__device__ __nv_bfloat16 g_xhi[BSZ * INCH];
__device__ __nv_bfloat16 g_xlo[BSZ * INCH];
__device__ __nv_bfloat16 g_whi[WROWS * INCH];
__device__ __nv_bfloat16 g_wlo[WROWS * INCH];
__device__ float g_hpart[KSPLIT][BSZ * OUTCH];
__device__ float g_h   [BSZ * OUTCH];
__device__ float g_hmul[BSZ * OUTCH];
__device__ float g_q   [OUTCH * BSZ];
__device__ float g_k   [OUTCH * BSZ];
__device__ float g_v   [OUTCH * BSZ];
__device__ float g_o   [OUTCH * BSZ];
__device__ float g_sum [2 * OUTCH];   // after reduce: BN affine scale A
__device__ float g_sq  [2 * OUTCH];   // after reduce: BN affine shift B

#define LOG2E 1.4426950408889634f

__device__ __forceinline__ float ex2(float x) {
    float y;
    asm("ex2.approx.ftz.f32 %0, %1;" : "=f"(y) : "f"(x));
    return y;
}

// exp2 on the FMA/ALU pipes (MUFU-free): magic-round + deg-5 Horner + exponent IADD.
__device__ __forceinline__ float exp2_poly(float x) {
    float t = x + 12582912.0f;            // 1.5*2^23: n = round(x) in low mantissa bits
    int   e = __float_as_int(t) << 23;
    float n = t - 12582912.0f;
    float f = x - n;                      // f in [-0.5, 0.5]
    float p = 1.3333558146e-3f;
    p = fmaf(p, f, 9.6181291076e-3f);
    p = fmaf(p, f, 5.5504108665e-2f);
    p = fmaf(p, f, 2.4022650696e-1f);
    p = fmaf(p, f, 6.9314718056e-1f);
    p = fmaf(p, f, 1.0f);
    return __int_as_float(__float_as_int(p) + e);
}

// ---------------- kernel 0: fp32 -> bf16 hi/lo split ----------------
__global__ __launch_bounds__(256) void prep_kernel(const float* __restrict__ x,
                                                   const float* __restrict__ w) {
    const int gid = blockIdx.x * 256 + threadIdx.x;
    const int XQ = BSZ * INCH / 4;
    const int WQ = WROWS * INCH / 4;
    float4 v;
    uint2 *hid, *lod;
    if (gid < XQ) {
        v = ((const float4*)x)[gid];
        hid = (uint2*)g_xhi + gid; lod = (uint2*)g_xlo + gid;
    } else {
        int q = gid - XQ;
        if (q >= WQ) return;
        v = (q < OUTCH * (INCH / 4)) ? ((const float4*)w)[q] : make_float4(0.f, 0.f, 0.f, 0.f);
        hid = (uint2*)g_whi + q; lod = (uint2*)g_wlo + q;
    }
    float fv[4] = {v.x, v.y, v.z, v.w};
    unsigned short hs[4], ls[4];
    #pragma unroll
    for (int i = 0; i < 4; i++) {
        __nv_bfloat16 h = __float2bfloat16(fv[i]);
        __nv_bfloat16 l = __float2bfloat16(fv[i] - __bfloat162float(h));
        hs[i] = __bfloat16_as_ushort(h);
        ls[i] = __bfloat16_as_ushort(l);
    }
    uint2 H, L;
    H.x = ((unsigned)hs[1] << 16) | hs[0]; H.y = ((unsigned)hs[3] << 16) | hs[2];
    L.x = ((unsigned)ls[1] << 16) | ls[0]; L.y = ((unsigned)ls[3] << 16) | ls[2];
    *hid = H; *lod = L;
}

// ---------------- mma.sync m16n8k16 bf16 ----------------
__device__ __forceinline__ void mma16816(float* c, const unsigned* a, const unsigned* b) {
    asm volatile(
        "mma.sync.aligned.m16n8k16.row.col.f32.bf16.bf16.f32 "
        "{%0,%1,%2,%3}, {%4,%5,%6,%7}, {%8,%9}, {%0,%1,%2,%3};\n"
        : "+f"(c[0]), "+f"(c[1]), "+f"(c[2]), "+f"(c[3])
        : "r"(a[0]), "r"(a[1]), "r"(a[2]), "r"(a[3]), "r"(b[0]), "r"(b[1]));
}

#define PITCH   36
#define P_AH    0
#define P_AL    2304
#define P_BH    4608
#define P_BL    6912
#define STAGE_W 9216
#define GSMEM   (2 * STAGE_W * 4)

__device__ __forceinline__ void fetch_stage(uint4* ld, int bm, int bn, int kb8, int s, int tid) {
    const uint4* XH4 = (const uint4*)g_xhi;
    const uint4* XL4 = (const uint4*)g_xlo;
    const uint4* WH4 = (const uint4*)g_whi;
    const uint4* WL4 = (const uint4*)g_wlo;
    const int w = tid & 7;
    const int rr = tid >> 3;
    const size_t col = kb8 + s * 8 + w;
    ld[0] = XH4[(size_t)(bm + rr)      * 256 + col];
    ld[1] = XH4[(size_t)(bm + rr + 32) * 256 + col];
    ld[2] = XL4[(size_t)(bm + rr)      * 256 + col];
    ld[3] = XL4[(size_t)(bm + rr + 32) * 256 + col];
    ld[4] = WH4[(size_t)(bn + rr)      * 256 + col];
    ld[5] = WH4[(size_t)(bn + rr + 32) * 256 + col];
    ld[6] = WL4[(size_t)(bn + rr)      * 256 + col];
    ld[7] = WL4[(size_t)(bn + rr + 32) * 256 + col];
}

__device__ __forceinline__ void store_stage(unsigned* swp, const uint4* ld, int tid) {
    const int w = tid & 7;
    const int rr = tid >> 3;
    uint4* d = (uint4*)swp;
    d[(P_AH / 4) + rr * 9 + w]            = ld[0];
    d[(P_AH / 4) + (rr + 32) * 9 + w]     = ld[1];
    d[(P_AL / 4) + rr * 9 + w]            = ld[2];
    d[(P_AL / 4) + (rr + 32) * 9 + w]     = ld[3];
    d[(P_BH / 4) + rr * 9 + w]            = ld[4];
    d[(P_BH / 4) + (rr + 32) * 9 + w]     = ld[5];
    d[(P_BL / 4) + rr * 9 + w]            = ld[6];
    d[(P_BL / 4) + (rr + 32) * 9 + w]     = ld[7];
}

// ---------------- kernel 1: smem-staged bf16-split tensor GEMM ----------------
__global__ __launch_bounds__(256) void gemm_mma_kernel() {
    extern __shared__ unsigned smem_dyn[];
    const int tid  = threadIdx.x;
    const int lane = tid & 31;
    const int warp = tid >> 5;
    const int wm = warp & 3;
    const int wn = warp >> 2;
    const int bm = blockIdx.y * 64;
    const int bn = blockIdx.x * 64;
    const int kb8 = blockIdx.z * (KSLICE / 8);

    float acc[4][4];
    #pragma unroll
    for (int j = 0; j < 4; j++)
        #pragma unroll
        for (int i = 0; i < 4; i++) acc[j][i] = 0.f;

    const int r  = lane >> 2;
    const int kq = lane & 3;
    const int arow0 = (wm * 16 + r) * PITCH + kq;
    const int arow8 = arow0 + 8 * PITCH;

    uint4 ld[8];
    fetch_stage(ld, bm, bn, kb8, 0, tid);
    store_stage(smem_dyn, ld, tid);
    __syncthreads();

    #pragma unroll
    for (int s = 0; s < 8; s++) {
        if (s + 1 < 8) fetch_stage(ld, bm, bn, kb8, s + 1, tid);

        const unsigned* sw = smem_dyn + (s & 1) * STAGE_W;
        #pragma unroll
        for (int t = 0; t < 4; t++) {
            const int ka = t * 8;
            unsigned ah[4], al[4];
            ah[0] = sw[P_AH + arow0 + ka];     ah[1] = sw[P_AH + arow8 + ka];
            ah[2] = sw[P_AH + arow0 + ka + 4]; ah[3] = sw[P_AH + arow8 + ka + 4];
            al[0] = sw[P_AL + arow0 + ka];     al[1] = sw[P_AL + arow8 + ka];
            al[2] = sw[P_AL + arow0 + ka + 4]; al[3] = sw[P_AL + arow8 + ka + 4];
            #pragma unroll
            for (int j = 0; j < 4; j++) {
                const int brow = (wn * 32 + j * 8 + r) * PITCH + kq;
                unsigned bh[2], bl[2];
                bh[0] = sw[P_BH + brow + ka]; bh[1] = sw[P_BH + brow + ka + 4];
                bl[0] = sw[P_BL + brow + ka]; bl[1] = sw[P_BL + brow + ka + 4];
                mma16816(acc[j], ah, bh);
                mma16816(acc[j], ah, bl);
                mma16816(acc[j], al, bh);
            }
        }

        if (s + 1 < 8) {
            __syncthreads();
            store_stage(smem_dyn + ((s + 1) & 1) * STAGE_W, ld, tid);
            __syncthreads();
        }
    }

    float* dst = g_hpart[blockIdx.z];
    const int r0 = bm + wm * 16 + (lane >> 2);
    #pragma unroll
    for (int j = 0; j < 4; j++) {
        const int c = bn + wn * 32 + j * 8 + 2 * (lane & 3);
        if (c < OUTCH) {
            *(float2*)(dst + (size_t)r0 * OUTCH + c)       = make_float2(acc[j][0], acc[j][1]);
            *(float2*)(dst + (size_t)(r0 + 8) * OUTCH + c) = make_float2(acc[j][2], acc[j][3]);
        }
    }
}

// ---------------- kernel 2: reduce split-K -> g_h + BN affine (A,B) precompute ----------------
__global__ __launch_bounds__(256) void reduce_stats_kernel(const float* __restrict__ gamma,
                                                           const float* __restrict__ beta) {
    __shared__ float ssum[8][32];
    __shared__ float ssq [8][32];
    const int c = threadIdx.x & 31, g = threadIdx.x >> 5;
    const int cg = blockIdx.x * 32 + c;
    const int chunk = blockIdx.y;
    const bool valid = cg < OUTCH;

    float s = 0.f, sq = 0.f;
    if (valid) {
        #pragma unroll 4
        for (int r = 0; r < 40; r++) {
            int row = chunk * CHROWS + g * 40 + r;
            size_t idx = (size_t)row * OUTCH + cg;
            float h = g_hpart[0][idx] + g_hpart[1][idx] + g_hpart[2][idx] + g_hpart[3][idx];
            g_h[idx] = h;
            s += h; sq += h * h;
        }
    }
    ssum[g][c] = s; ssq[g][c] = sq;
    __syncthreads();
    if (g == 0 && valid) {
        float ts = 0.f, tq = 0.f;
        #pragma unroll
        for (int i = 0; i < 8; i++) { ts += ssum[i][c]; tq += ssq[i][c]; }
        float mean = ts * (1.f / CHROWS);
        float var  = tq * (1.f / CHROWS) - mean * mean;
        float A = gamma[cg] * rsqrtf(var + 1e-5f);
        g_sum[chunk * OUTCH + cg] = A;                      // scale
        g_sq [chunk * OUTCH + cg] = beta[cg] - mean * A;    // shift
    }
}

// ---------------- kernel 3: BN affine + prior-mul + q/k/v (coalesced transpose) ----------------
__global__ __launch_bounds__(256) void bn_qkv_kernel(const float* __restrict__ prior,
                                                     const float* __restrict__ ipw,
                                                     const float* __restrict__ ipb) {
    __shared__ float qs[32][33];
    __shared__ float ks[32][33];
    __shared__ float vs[32][33];
    const int tid = threadIdx.x;
    const int ni = tid & 7, li = tid >> 3;
    const int nb = blockIdx.x, lb = blockIdx.y;
    const int n = nb * 8 + ni;
    const int l = lb * 32 + li;

    if (n < NS) {
        const int c0 = n * 4;
        const int chunk = l / CHROWS;
        float4 Ar = *(const float4*)(g_sum + chunk * OUTCH + c0);
        float4 Br = *(const float4*)(g_sq  + chunk * OUTCH + c0);
        float4 hr = *(const float4*)(g_h + (size_t)l * OUTCH + c0);
        float4 pr = *(const float4*)(prior + (size_t)l * OUTCH + c0);
        float Av[4] = {Ar.x, Ar.y, Ar.z, Ar.w};
        float Bv[4] = {Br.x, Br.y, Br.z, Br.w};
        float hv[4] = {hr.x, hr.y, hr.z, hr.w};
        float pv[4] = {pr.x, pr.y, pr.z, pr.w};
        float hm[4];
        #pragma unroll
        for (int e = 0; e < 4; e++)
            hm[e] = pv[e] * fmaf(hv[e], Av[e], Bv[e]);
        *(float4*)(g_hmul + (size_t)l * OUTCH + c0) = make_float4(hm[0], hm[1], hm[2], hm[3]);
        #pragma unroll
        for (int e = 0; e < 4; e++) {
            float q = ipb[e], k = ipb[4 + e], v = ipb[8 + e];
            #pragma unroll
            for (int e2 = 0; e2 < 4; e2++) {
                q = fmaf(ipw[e * 4 + e2],       hm[e2], q);
                k = fmaf(ipw[(4 + e) * 4 + e2], pv[e2], k);
                v = fmaf(ipw[(8 + e) * 4 + e2], pv[e2], v);
            }
            qs[ni * 4 + e][li] = q * LOG2E;
            ks[ni * 4 + e][li] = k;
            vs[ni * 4 + e][li] = v;
        }
    }
    __syncthreads();
    const int lo = tid & 31;
    #pragma unroll
    for (int p = 0; p < 4; p++) {
        int cl = (tid >> 5) + p * 8;
        int cc = nb * 32 + cl;
        if (cc < OUTCH) {
            size_t off = (size_t)cc * BSZ + lb * 32 + lo;
            g_q[off] = qs[cl][lo];
            g_k[off] = ks[cl][lo];
            g_v[off] = vs[cl][lo];
        }
    }
}

// ---------------- kernel 4: per-channel attention, hybrid MUFU/poly exp ----------------
__global__ __launch_bounds__(640) void attn_kernel() {
    __shared__ __align__(16) float ks[BSZ];
    __shared__ __align__(16) float vs[BSZ];
    const int c = blockIdx.x, t = threadIdx.x;
    ks[t] = g_k[(size_t)c * BSZ + t];
    vs[t] = g_v[(size_t)c * BSZ + t];
    __syncthreads();

    const float ql = g_q[(size_t)c * BSZ + t];
    unsigned long long qq;
    asm("mov.b64 %0, {%1, %1};" : "=l"(qq) : "f"(ql));
    unsigned long long d01 = 0ull, d23 = 0ull, n01 = 0ull, n23 = 0ull;
    const ulonglong2* k2 = (const ulonglong2*)ks;
    const ulonglong2* v2 = (const ulonglong2*)vs;
    #pragma unroll 4
    for (int s = 0; s < BSZ / 4; s++) {
        ulonglong2 kk = k2[s], vv = v2[s];
        unsigned long long p01, p23;
        asm("mul.rn.f32x2 %0, %1, %2;" : "=l"(p01) : "l"(kk.x), "l"(qq));
        asm("mul.rn.f32x2 %0, %1, %2;" : "=l"(p23) : "l"(kk.y), "l"(qq));
        float x0, x1, x2, x3;
        asm("mov.b64 {%0, %1}, %2;" : "=f"(x0), "=f"(x1) : "l"(p01));
        asm("mov.b64 {%0, %1}, %2;" : "=f"(x2), "=f"(x3) : "l"(p23));
        // 3 MUFU + 1 FMA-pipe poly: offload past the MUFU pipe floor
        float e0 = ex2(x0), e1 = ex2(x1), e2 = ex2(x2);
        float e3 = exp2_poly(x3);
        unsigned long long e01, e23;
        asm("mov.b64 %0, {%1, %2};" : "=l"(e01) : "f"(e0), "f"(e1));
        asm("mov.b64 %0, {%1, %2};" : "=l"(e23) : "f"(e2), "f"(e3));
        asm("add.rn.f32x2 %0, %0, %1;" : "+l"(d01) : "l"(e01));
        asm("add.rn.f32x2 %0, %0, %1;" : "+l"(d23) : "l"(e23));
        asm("fma.rn.f32x2 %0, %1, %2, %0;" : "+l"(n01) : "l"(e01), "l"(vv.x));
        asm("fma.rn.f32x2 %0, %1, %2, %0;" : "+l"(n23) : "l"(e23), "l"(vv.y));
    }
    float da, db, dc, dd, na, nb, nc, nd;
    asm("mov.b64 {%0, %1}, %2;" : "=f"(da), "=f"(db) : "l"(d01));
    asm("mov.b64 {%0, %1}, %2;" : "=f"(dc), "=f"(dd) : "l"(d23));
    asm("mov.b64 {%0, %1}, %2;" : "=f"(na), "=f"(nb) : "l"(n01));
    asm("mov.b64 {%0, %1}, %2;" : "=f"(nc), "=f"(nd) : "l"(n23));
    g_o[(size_t)c * BSZ + t] = ((na + nb) + (nc + nd)) / ((da + db) + (dc + dd));
}

// ---------------- kernel 5: out_proj + residual + row softmax ----------------
__global__ __launch_bounds__(256) void epi_kernel(const float* __restrict__ opw,
                                                  const float* __restrict__ opb,
                                                  float* __restrict__ out) {
    __shared__ float orow[OUTCH];
    __shared__ float sh[OUTCH];
    __shared__ float rbuf[8];
    const int l = blockIdx.x, tid = threadIdx.x;

    for (int c = tid; c < OUTCH; c += 256) orow[c] = g_o[(size_t)c * BSZ + l];
    __syncthreads();

    float lmax = -1e30f;
    for (int c = tid; c < OUTCH; c += 256) {
        int n = c >> 2, e = c & 3;
        float y = opb[e];
        #pragma unroll
        for (int e2 = 0; e2 < 4; e2++) y = fmaf(opw[e * 4 + e2], orow[n * 4 + e2], y);
        float lg = g_hmul[(size_t)l * OUTCH + c] + y;
        sh[c] = lg;
        lmax = fmaxf(lmax, lg);
    }
    #pragma unroll
    for (int o = 16; o; o >>= 1) lmax = fmaxf(lmax, __shfl_xor_sync(0xFFFFFFFFu, lmax, o));
    if ((tid & 31) == 0) rbuf[tid >> 5] = lmax;
    __syncthreads();
    float bmax = rbuf[0];
    #pragma unroll
    for (int i = 1; i < 8; i++) bmax = fmaxf(bmax, rbuf[i]);
    __syncthreads();

    float sum = 0.f;
    for (int c = tid; c < OUTCH; c += 256) {
        float e = ex2((sh[c] - bmax) * LOG2E);
        sh[c] = e;
        sum += e;
    }
    #pragma unroll
    for (int o = 16; o; o >>= 1) sum += __shfl_xor_sync(0xFFFFFFFFu, sum, o);
    if ((tid & 31) == 0) rbuf[tid >> 5] = sum;
    __syncthreads();
    float bsum = 0.f;
    #pragma unroll
    for (int i = 0; i < 8; i++) bsum += rbuf[i];
    float inv = 1.f / bsum;
    for (int c = tid; c < OUTCH; c += 256) out[(size_t)l * OUTCH + c] = sh[c] * inv;
}

// ---------------- launch ----------------
extern "C" void kernel_launch(void* const* d_in, const int* in_sizes, int n_in,
                              void* d_out, int out_size) {
    const float* x     = (const float*)d_in[0];
    const float* prior = (const float*)d_in[1];
    const float* w_lin = (const float*)d_in[2];
    const float* gamma = (const float*)d_in[3];
    const float* beta  = (const float*)d_in[4];
    const float* ipw   = (const float*)d_in[5];
    const float* ipb   = (const float*)d_in[6];
    const float* opw   = (const float*)d_in[7];
    const float* opb   = (const float*)d_in[8];
    float* out = (float*)d_out;

    cudaFuncSetAttribute(gemm_mma_kernel, cudaFuncAttributeMaxDynamicSharedMemorySize, GSMEM);

    prep_kernel<<<(BSZ * INCH / 4 + WROWS * INCH / 4) / 256, 256>>>(x, w_lin);
    gemm_mma_kernel<<<dim3(WROWS / 64, BSZ / 64, KSPLIT), 256, GSMEM>>>();
    reduce_stats_kernel<<<dim3((OUTCH + 31) / 32, 2), 256>>>(gamma, beta);
    bn_qkv_kernel<<<dim3((NS + 7) / 8, BSZ / 32), 256>>>(prior, ipw, ipb);
    attn_kernel<<<OUTCH, BSZ>>>();
    epi_kernel<<<BSZ, 256>>>(opw, opb, out);
}

// round 13
// speedup vs baseline: 1.2234x; 1.2234x over previous
#include <cuda_runtime.h>
#include <cuda_bf16.h>

#define BSZ    640
#define INCH   2048
#define OUTCH  696
#define NS     174
#define CHROWS 320
#define WROWS  704              // OUTCH padded to 64
#define KSPLIT 4
#define KSLICE (INCH / KSPLIT)  // 512

// ---------------- scratch ----------------
__device__ __nv_bfloat16 g_xhi[BSZ * INCH];
__device__ __nv_bfloat16 g_xlo[BSZ * INCH];
__device__ __nv_bfloat16 g_whi[WROWS * INCH];
__device__ __nv_bfloat16 g_wlo[WROWS * INCH];
__device__ float g_hpart[KSPLIT][BSZ * OUTCH];
__device__ float g_h   [BSZ * OUTCH];
__device__ float g_hmul[BSZ * OUTCH];
__device__ float g_q   [OUTCH * BSZ];
__device__ float g_k   [OUTCH * BSZ];
__device__ float g_v   [OUTCH * BSZ];
__device__ float g_o   [OUTCH * BSZ];
__device__ float g_sum [2 * OUTCH];   // after reduce: BN affine scale A
__device__ float g_sq  [2 * OUTCH];   // after reduce: BN affine shift B

#define LOG2E 1.4426950408889634f

__device__ __forceinline__ float ex2(float x) {
    float y;
    asm("ex2.approx.ftz.f32 %0, %1;" : "=f"(y) : "f"(x));
    return y;
}

__device__ __forceinline__ unsigned smem_to_u32(const void* p) {
    unsigned a;
    asm("{ .reg .u64 t; cvta.to.shared.u64 t, %1; cvt.u32.u64 %0, t; }" : "=r"(a) : "l"(p));
    return a;
}

#define CP_ASYNC16(dst_u32, src_ptr) \
    asm volatile("cp.async.cg.shared.global [%0], [%1], 16;" :: "r"(dst_u32), "l"(src_ptr) : "memory")
#define CP_COMMIT() asm volatile("cp.async.commit_group;" ::: "memory")
#define CP_WAIT0()  asm volatile("cp.async.wait_group 0;" ::: "memory")

// ---------------- kernel 0: fp32 -> bf16 hi/lo split ----------------
__global__ __launch_bounds__(256) void prep_kernel(const float* __restrict__ x,
                                                   const float* __restrict__ w) {
    const int gid = blockIdx.x * 256 + threadIdx.x;
    const int XQ = BSZ * INCH / 4;
    const int WQ = WROWS * INCH / 4;
    float4 v;
    uint2 *hid, *lod;
    if (gid < XQ) {
        v = ((const float4*)x)[gid];
        hid = (uint2*)g_xhi + gid; lod = (uint2*)g_xlo + gid;
    } else {
        int q = gid - XQ;
        if (q >= WQ) return;
        v = (q < OUTCH * (INCH / 4)) ? ((const float4*)w)[q] : make_float4(0.f, 0.f, 0.f, 0.f);
        hid = (uint2*)g_whi + q; lod = (uint2*)g_wlo + q;
    }
    float fv[4] = {v.x, v.y, v.z, v.w};
    unsigned short hs[4], ls[4];
    #pragma unroll
    for (int i = 0; i < 4; i++) {
        __nv_bfloat16 h = __float2bfloat16(fv[i]);
        __nv_bfloat16 l = __float2bfloat16(fv[i] - __bfloat162float(h));
        hs[i] = __bfloat16_as_ushort(h);
        ls[i] = __bfloat16_as_ushort(l);
    }
    uint2 H, L;
    H.x = ((unsigned)hs[1] << 16) | hs[0]; H.y = ((unsigned)hs[3] << 16) | hs[2];
    L.x = ((unsigned)ls[1] << 16) | ls[0]; L.y = ((unsigned)ls[3] << 16) | ls[2];
    *hid = H; *lod = L;
}

// ---------------- mma.sync m16n8k16 bf16 ----------------
__device__ __forceinline__ void mma16816(float* c, const unsigned* a, const unsigned* b) {
    asm volatile(
        "mma.sync.aligned.m16n8k16.row.col.f32.bf16.bf16.f32 "
        "{%0,%1,%2,%3}, {%4,%5,%6,%7}, {%8,%9}, {%0,%1,%2,%3};\n"
        : "+f"(c[0]), "+f"(c[1]), "+f"(c[2]), "+f"(c[3])
        : "r"(a[0]), "r"(a[1]), "r"(a[2]), "r"(a[3]), "r"(b[0]), "r"(b[1]));
}

#define PITCH   36
#define P_AH    0
#define P_AL    2304
#define P_BH    4608
#define P_BL    6912
#define STAGE_W 9216
#define GSMEM   (2 * STAGE_W * 4)

// issue one BK=64 stage via cp.async: 8 x 16B per thread, fully coalesced.
__device__ __forceinline__ void issue_stage(unsigned sdst, int bm, int bn, int kb8, int s, int tid) {
    const uint4* XH4 = (const uint4*)g_xhi;
    const uint4* XL4 = (const uint4*)g_xlo;
    const uint4* WH4 = (const uint4*)g_whi;
    const uint4* WL4 = (const uint4*)g_wlo;
    const int w = tid & 7;
    const int rr = tid >> 3;
    const size_t col = kb8 + s * 8 + w;
    const unsigned d0 = sdst + (unsigned)(P_AH * 4 + (rr * 9 + w) * 16);
    const unsigned d1 = sdst + (unsigned)(P_AH * 4 + ((rr + 32) * 9 + w) * 16);
    const unsigned d2 = sdst + (unsigned)(P_AL * 4 + (rr * 9 + w) * 16);
    const unsigned d3 = sdst + (unsigned)(P_AL * 4 + ((rr + 32) * 9 + w) * 16);
    const unsigned d4 = sdst + (unsigned)(P_BH * 4 + (rr * 9 + w) * 16);
    const unsigned d5 = sdst + (unsigned)(P_BH * 4 + ((rr + 32) * 9 + w) * 16);
    const unsigned d6 = sdst + (unsigned)(P_BL * 4 + (rr * 9 + w) * 16);
    const unsigned d7 = sdst + (unsigned)(P_BL * 4 + ((rr + 32) * 9 + w) * 16);
    CP_ASYNC16(d0, XH4 + (size_t)(bm + rr)      * 256 + col);
    CP_ASYNC16(d1, XH4 + (size_t)(bm + rr + 32) * 256 + col);
    CP_ASYNC16(d2, XL4 + (size_t)(bm + rr)      * 256 + col);
    CP_ASYNC16(d3, XL4 + (size_t)(bm + rr + 32) * 256 + col);
    CP_ASYNC16(d4, WH4 + (size_t)(bn + rr)      * 256 + col);
    CP_ASYNC16(d5, WH4 + (size_t)(bn + rr + 32) * 256 + col);
    CP_ASYNC16(d6, WL4 + (size_t)(bn + rr)      * 256 + col);
    CP_ASYNC16(d7, WL4 + (size_t)(bn + rr + 32) * 256 + col);
}

// ---------------- kernel 1: cp.async-staged bf16-split tensor GEMM ----------------
__global__ __launch_bounds__(256) void gemm_mma_kernel() {
    extern __shared__ unsigned smem_dyn[];
    const unsigned sbase = smem_to_u32(smem_dyn);
    const int tid  = threadIdx.x;
    const int lane = tid & 31;
    const int warp = tid >> 5;
    const int wm = warp & 3;
    const int wn = warp >> 2;
    const int bm = blockIdx.y * 64;
    const int bn = blockIdx.x * 64;
    const int kb8 = blockIdx.z * (KSLICE / 8);

    float acc[4][4];
    #pragma unroll
    for (int j = 0; j < 4; j++)
        #pragma unroll
        for (int i = 0; i < 4; i++) acc[j][i] = 0.f;

    const int r  = lane >> 2;
    const int kq = lane & 3;
    const int arow0 = (wm * 16 + r) * PITCH + kq;
    const int arow8 = arow0 + 8 * PITCH;

    issue_stage(sbase, bm, bn, kb8, 0, tid);
    CP_COMMIT();
    CP_WAIT0();
    __syncthreads();

    #pragma unroll
    for (int s = 0; s < 8; s++) {
        // prefetch next stage into the other buffer (safe: that buffer's compute
        // finished before the __syncthreads that ended the previous iteration)
        if (s + 1 < 8) {
            issue_stage(sbase + ((s + 1) & 1) * (STAGE_W * 4), bm, bn, kb8, s + 1, tid);
            CP_COMMIT();
        }

        const unsigned* sw = smem_dyn + (s & 1) * STAGE_W;
        #pragma unroll
        for (int t = 0; t < 4; t++) {
            const int ka = t * 8;
            unsigned ah[4], al[4];
            ah[0] = sw[P_AH + arow0 + ka];     ah[1] = sw[P_AH + arow8 + ka];
            ah[2] = sw[P_AH + arow0 + ka + 4]; ah[3] = sw[P_AH + arow8 + ka + 4];
            al[0] = sw[P_AL + arow0 + ka];     al[1] = sw[P_AL + arow8 + ka];
            al[2] = sw[P_AL + arow0 + ka + 4]; al[3] = sw[P_AL + arow8 + ka + 4];
            #pragma unroll
            for (int j = 0; j < 4; j++) {
                const int brow = (wn * 32 + j * 8 + r) * PITCH + kq;
                unsigned bh[2], bl[2];
                bh[0] = sw[P_BH + brow + ka]; bh[1] = sw[P_BH + brow + ka + 4];
                bl[0] = sw[P_BL + brow + ka]; bl[1] = sw[P_BL + brow + ka + 4];
                mma16816(acc[j], ah, bh);
                mma16816(acc[j], ah, bl);
                mma16816(acc[j], al, bh);
            }
        }

        if (s + 1 < 8) {
            CP_WAIT0();
            __syncthreads();
        }
    }

    float* dst = g_hpart[blockIdx.z];
    const int r0 = bm + wm * 16 + (lane >> 2);
    #pragma unroll
    for (int j = 0; j < 4; j++) {
        const int c = bn + wn * 32 + j * 8 + 2 * (lane & 3);
        if (c < OUTCH) {
            *(float2*)(dst + (size_t)r0 * OUTCH + c)       = make_float2(acc[j][0], acc[j][1]);
            *(float2*)(dst + (size_t)(r0 + 8) * OUTCH + c) = make_float2(acc[j][2], acc[j][3]);
        }
    }
}

// ---------------- kernel 2: reduce split-K -> g_h + BN affine (A,B) precompute ----------------
__global__ __launch_bounds__(256) void reduce_stats_kernel(const float* __restrict__ gamma,
                                                           const float* __restrict__ beta) {
    __shared__ float ssum[8][32];
    __shared__ float ssq [8][32];
    const int c = threadIdx.x & 31, g = threadIdx.x >> 5;
    const int cg = blockIdx.x * 32 + c;
    const int chunk = blockIdx.y;
    const bool valid = cg < OUTCH;

    float s = 0.f, sq = 0.f;
    if (valid) {
        #pragma unroll 4
        for (int r = 0; r < 40; r++) {
            int row = chunk * CHROWS + g * 40 + r;
            size_t idx = (size_t)row * OUTCH + cg;
            float h = g_hpart[0][idx] + g_hpart[1][idx] + g_hpart[2][idx] + g_hpart[3][idx];
            g_h[idx] = h;
            s += h; sq += h * h;
        }
    }
    ssum[g][c] = s; ssq[g][c] = sq;
    __syncthreads();
    if (g == 0 && valid) {
        float ts = 0.f, tq = 0.f;
        #pragma unroll
        for (int i = 0; i < 8; i++) { ts += ssum[i][c]; tq += ssq[i][c]; }
        float mean = ts * (1.f / CHROWS);
        float var  = tq * (1.f / CHROWS) - mean * mean;
        float A = gamma[cg] * rsqrtf(var + 1e-5f);
        g_sum[chunk * OUTCH + cg] = A;                      // scale
        g_sq [chunk * OUTCH + cg] = beta[cg] - mean * A;    // shift
    }
}

// ---------------- kernel 3: BN affine + prior-mul + q/k/v (coalesced transpose) ----------------
__global__ __launch_bounds__(256) void bn_qkv_kernel(const float* __restrict__ prior,
                                                     const float* __restrict__ ipw,
                                                     const float* __restrict__ ipb) {
    __shared__ float qs[32][33];
    __shared__ float ks[32][33];
    __shared__ float vs[32][33];
    const int tid = threadIdx.x;
    const int ni = tid & 7, li = tid >> 3;
    const int nb = blockIdx.x, lb = blockIdx.y;
    const int n = nb * 8 + ni;
    const int l = lb * 32 + li;

    if (n < NS) {
        const int c0 = n * 4;
        const int chunk = l / CHROWS;
        float4 Ar = *(const float4*)(g_sum + chunk * OUTCH + c0);
        float4 Br = *(const float4*)(g_sq  + chunk * OUTCH + c0);
        float4 hr = *(const float4*)(g_h + (size_t)l * OUTCH + c0);
        float4 pr = *(const float4*)(prior + (size_t)l * OUTCH + c0);
        float Av[4] = {Ar.x, Ar.y, Ar.z, Ar.w};
        float Bv[4] = {Br.x, Br.y, Br.z, Br.w};
        float hv[4] = {hr.x, hr.y, hr.z, hr.w};
        float pv[4] = {pr.x, pr.y, pr.z, pr.w};
        float hm[4];
        #pragma unroll
        for (int e = 0; e < 4; e++)
            hm[e] = pv[e] * fmaf(hv[e], Av[e], Bv[e]);
        *(float4*)(g_hmul + (size_t)l * OUTCH + c0) = make_float4(hm[0], hm[1], hm[2], hm[3]);
        #pragma unroll
        for (int e = 0; e < 4; e++) {
            float q = ipb[e], k = ipb[4 + e], v = ipb[8 + e];
            #pragma unroll
            for (int e2 = 0; e2 < 4; e2++) {
                q = fmaf(ipw[e * 4 + e2],       hm[e2], q);
                k = fmaf(ipw[(4 + e) * 4 + e2], pv[e2], k);
                v = fmaf(ipw[(8 + e) * 4 + e2], pv[e2], v);
            }
            qs[ni * 4 + e][li] = q * LOG2E;
            ks[ni * 4 + e][li] = k;
            vs[ni * 4 + e][li] = v;
        }
    }
    __syncthreads();
    const int lo = tid & 31;
    #pragma unroll
    for (int p = 0; p < 4; p++) {
        int cl = (tid >> 5) + p * 8;
        int cc = nb * 32 + cl;
        if (cc < OUTCH) {
            size_t off = (size_t)cc * BSZ + lb * 32 + lo;
            g_q[off] = qs[cl][lo];
            g_k[off] = ks[cl][lo];
            g_v[off] = vs[cl][lo];
        }
    }
}

// ---------------- kernel 4: per-channel attention (pure-MUFU f32x2 — proven fastest) ----------
__global__ __launch_bounds__(640) void attn_kernel() {
    __shared__ __align__(16) float ks[BSZ];
    __shared__ __align__(16) float vs[BSZ];
    const int c = blockIdx.x, t = threadIdx.x;
    ks[t] = g_k[(size_t)c * BSZ + t];
    vs[t] = g_v[(size_t)c * BSZ + t];
    __syncthreads();

    const float ql = g_q[(size_t)c * BSZ + t];
    unsigned long long qq;
    asm("mov.b64 %0, {%1, %1};" : "=l"(qq) : "f"(ql));
    unsigned long long d01 = 0ull, d23 = 0ull, n01 = 0ull, n23 = 0ull;
    const ulonglong2* k2 = (const ulonglong2*)ks;
    const ulonglong2* v2 = (const ulonglong2*)vs;
    #pragma unroll 4
    for (int s = 0; s < BSZ / 4; s++) {
        ulonglong2 kk = k2[s], vv = v2[s];
        unsigned long long p01, p23;
        asm("mul.rn.f32x2 %0, %1, %2;" : "=l"(p01) : "l"(kk.x), "l"(qq));
        asm("mul.rn.f32x2 %0, %1, %2;" : "=l"(p23) : "l"(kk.y), "l"(qq));
        float x0, x1, x2, x3;
        asm("mov.b64 {%0, %1}, %2;" : "=f"(x0), "=f"(x1) : "l"(p01));
        asm("mov.b64 {%0, %1}, %2;" : "=f"(x2), "=f"(x3) : "l"(p23));
        float e0 = ex2(x0), e1 = ex2(x1), e2 = ex2(x2), e3 = ex2(x3);
        unsigned long long e01, e23;
        asm("mov.b64 %0, {%1, %2};" : "=l"(e01) : "f"(e0), "f"(e1));
        asm("mov.b64 %0, {%1, %2};" : "=l"(e23) : "f"(e2), "f"(e3));
        asm("add.rn.f32x2 %0, %0, %1;" : "+l"(d01) : "l"(e01));
        asm("add.rn.f32x2 %0, %0, %1;" : "+l"(d23) : "l"(e23));
        asm("fma.rn.f32x2 %0, %1, %2, %0;" : "+l"(n01) : "l"(e01), "l"(vv.x));
        asm("fma.rn.f32x2 %0, %1, %2, %0;" : "+l"(n23) : "l"(e23), "l"(vv.y));
    }
    float da, db, dc, dd, na, nb, nc, nd;
    asm("mov.b64 {%0, %1}, %2;" : "=f"(da), "=f"(db) : "l"(d01));
    asm("mov.b64 {%0, %1}, %2;" : "=f"(dc), "=f"(dd) : "l"(d23));
    asm("mov.b64 {%0, %1}, %2;" : "=f"(na), "=f"(nb) : "l"(n01));
    asm("mov.b64 {%0, %1}, %2;" : "=f"(nc), "=f"(nd) : "l"(n23));
    g_o[(size_t)c * BSZ + t] = ((na + nb) + (nc + nd)) / ((da + db) + (dc + dd));
}

// ---------------- kernel 5: out_proj + residual + row softmax ----------------
__global__ __launch_bounds__(256) void epi_kernel(const float* __restrict__ opw,
                                                  const float* __restrict__ opb,
                                                  float* __restrict__ out) {
    __shared__ float orow[OUTCH];
    __shared__ float sh[OUTCH];
    __shared__ float rbuf[8];
    const int l = blockIdx.x, tid = threadIdx.x;

    for (int c = tid; c < OUTCH; c += 256) orow[c] = g_o[(size_t)c * BSZ + l];
    __syncthreads();

    float lmax = -1e30f;
    for (int c = tid; c < OUTCH; c += 256) {
        int n = c >> 2, e = c & 3;
        float y = opb[e];
        #pragma unroll
        for (int e2 = 0; e2 < 4; e2++) y = fmaf(opw[e * 4 + e2], orow[n * 4 + e2], y);
        float lg = g_hmul[(size_t)l * OUTCH + c] + y;
        sh[c] = lg;
        lmax = fmaxf(lmax, lg);
    }
    #pragma unroll
    for (int o = 16; o; o >>= 1) lmax = fmaxf(lmax, __shfl_xor_sync(0xFFFFFFFFu, lmax, o));
    if ((tid & 31) == 0) rbuf[tid >> 5] = lmax;
    __syncthreads();
    float bmax = rbuf[0];
    #pragma unroll
    for (int i = 1; i < 8; i++) bmax = fmaxf(bmax, rbuf[i]);
    __syncthreads();

    float sum = 0.f;
    for (int c = tid; c < OUTCH; c += 256) {
        float e = ex2((sh[c] - bmax) * LOG2E);
        sh[c] = e;
        sum += e;
    }
    #pragma unroll
    for (int o = 16; o; o >>= 1) sum += __shfl_xor_sync(0xFFFFFFFFu, sum, o);
    if ((tid & 31) == 0) rbuf[tid >> 5] = sum;
    __syncthreads();
    float bsum = 0.f;
    #pragma unroll
    for (int i = 0; i < 8; i++) bsum += rbuf[i];
    float inv = 1.f / bsum;
    for (int c = tid; c < OUTCH; c += 256) out[(size_t)l * OUTCH + c] = sh[c] * inv;
}

// ---------------- launch ----------------
extern "C" void kernel_launch(void* const* d_in, const int* in_sizes, int n_in,
                              void* d_out, int out_size) {
    const float* x     = (const float*)d_in[0];
    const float* prior = (const float*)d_in[1];
    const float* w_lin = (const float*)d_in[2];
    const float* gamma = (const float*)d_in[3];
    const float* beta  = (const float*)d_in[4];
    const float* ipw   = (const float*)d_in[5];
    const float* ipb   = (const float*)d_in[6];
    const float* opw   = (const float*)d_in[7];
    const float* opb   = (const float*)d_in[8];
    float* out = (float*)d_out;

    cudaFuncSetAttribute(gemm_mma_kernel, cudaFuncAttributeMaxDynamicSharedMemorySize, GSMEM);

    prep_kernel<<<(BSZ * INCH / 4 + WROWS * INCH / 4) / 256, 256>>>(x, w_lin);
    gemm_mma_kernel<<<dim3(WROWS / 64, BSZ / 64, KSPLIT), 256, GSMEM>>>();
    reduce_stats_kernel<<<dim3((OUTCH + 31) / 32, 2), 256>>>(gamma, beta);
    bn_qkv_kernel<<<dim3((NS + 7) / 8, BSZ / 32), 256>>>(prior, ipw, ipb);
    attn_kernel<<<OUTCH, BSZ>>>();
    epi_kernel<<<BSZ, 256>>>(opw, opb, out);
}